// round 4
// baseline (speedup 1.0000x reference)
#include <cuda_runtime.h>

#define LDIM 80
#define RDIM 80
#define BATCH 128
#define UD 128
#define CD 32
#define DD 416
#define NOUT 896
#define NDIAG 159
#define KB 52
#define KBP 53

// Full h storage for every cell (no rotation: pipelining-safe).
__device__ float    g_hfull[LDIM][RDIM][BATCH][UD];      // 419 MB
// Logits scratch, slot keyed by l (reuse protected by left-dependency).
__device__ float    g_logits[LDIM][BATCH][NOUT];         // 36.7 MB
// Pre-transposed tf32 inputs: (l, r, b, c).
__device__ unsigned g_sT[LDIM][RDIM][BATCH][CD];         // 104 MB
// Fragment-packed tf32 weights: jblk 0..111 = [Wr;Wz], 112..127 = [WU|Wij]
__device__ unsigned g_wpack[128][KBP][32][2];
// Dataflow flags (reset every run).
__device__ unsigned g_hflag[LDIM][RDIM][2];
__device__ unsigned g_lcnt[LDIM][2];
__device__ unsigned g_count;
__device__ unsigned g_sense;

__device__ __forceinline__ unsigned f2tf(float x) {
    unsigned u;
    asm("cvt.rna.tf32.f32 %0, %1;" : "=r"(u) : "f"(x));
    return u;
}

__device__ __forceinline__ void mma8(float* c, const uint4& a, const uint2& b) {
    asm volatile(
        "mma.sync.aligned.m16n8k8.row.col.f32.tf32.tf32.f32 "
        "{%0,%1,%2,%3}, {%4,%5,%6,%7}, {%8,%9}, {%0,%1,%2,%3};\n"
        : "+f"(c[0]), "+f"(c[1]), "+f"(c[2]), "+f"(c[3])
        : "r"(a.x), "r"(a.y), "r"(a.z), "r"(a.w), "r"(b.x), "r"(b.y));
}

__device__ __forceinline__ void gbar(int ncta, unsigned& sense) {
    __syncthreads();
    if (threadIdx.x == 0) {
        __threadfence();
        unsigned arrived = atomicAdd(&g_count, 1u) + 1u;
        if (arrived == (unsigned)ncta) {
            g_count = 0u;
            __threadfence();
            atomicAdd(&g_sense, 1u);
        } else {
            while ((int)(*(volatile unsigned*)&g_sense - (sense + 1u)) < 0) {
                __nanosleep(64);
            }
        }
    }
    sense += 1u;
    __syncthreads();
}

__global__ __launch_bounds__(256, 2) void spatial_gru_flow(
    const float* __restrict__ inputs, const float* __restrict__ Wr,
    const float* __restrict__ br, const float* __restrict__ Wz,
    const float* __restrict__ bz, const float* __restrict__ Wij,
    const float* __restrict__ bij, const float* __restrict__ WU,
    float* __restrict__ out, int ncta)
{
    extern __shared__ unsigned smem[];
    const int tid = threadIdx.x;
    const int cta = blockIdx.x;
    const int gtid = cta * 256 + tid;
    const int gstride = ncta * 256;
    unsigned sense = *(volatile unsigned*)&g_sense;

    // ---------------- stage 0: pack weights, transpose s, reset flags ------
    for (int idx = gtid; idx < 128 * KB * 32; idx += gstride) {
        const int lane = idx & 31;
        const int kblk = (idx >> 5) % KB;
        const int jblk = (idx >> 5) / KB;
        const int j = jblk * 8 + (lane >> 2);
        const int k = kblk * 8 + (lane & 3);
        float v0, v1;
        if (j < 384)      { v0 = Wr[j * DD + k];          v1 = Wr[j * DD + k + 4]; }
        else if (j < 896) { v0 = Wz[(j - 384) * DD + k];  v1 = Wz[(j - 384) * DD + k + 4]; }
        else {
            const int u = j - 896;
            v0 = (k < 384)     ? WU[u * 384 + k]     : Wij[u * 32 + (k - 384)];
            v1 = (k + 4 < 384) ? WU[u * 384 + k + 4] : Wij[u * 32 + (k - 380)];
        }
        g_wpack[jblk][kblk][lane][0] = f2tf(v0);
        g_wpack[jblk][kblk][lane][1] = f2tf(v1);
    }
    // transpose inputs (B,C,L,R) -> tf32 (L,R,B,C)
    for (int idx = gtid; idx < LDIM * RDIM * BATCH * (CD / 4); idx += gstride) {
        const int c4 = idx & 7;
        const int b  = (idx >> 3) & 127;
        const int r  = (idx >> 10) % RDIM;
        const int l  = (idx >> 10) / RDIM;
        const int c  = c4 * 4;
        const float* sp = inputs + (((size_t)b * CD + c) * LDIM + l) * RDIM + r;
        unsigned* dst = &g_sT[l][r][b][c];
        dst[0] = f2tf(sp[0]);
        dst[1] = f2tf(sp[LDIM * RDIM]);
        dst[2] = f2tf(sp[2 * LDIM * RDIM]);
        dst[3] = f2tf(sp[3 * LDIM * RDIM]);
    }
    for (int idx = gtid; idx < LDIM * RDIM * 2; idx += gstride)
        ((unsigned*)g_hflag)[idx] = 0u;
    for (int idx = gtid; idx < LDIM * 2; idx += gstride)
        ((unsigned*)g_lcnt)[idx] = 0u;
    gbar(ncta, sense);

    const int warp = tid >> 5, lane = tid & 31;
    const int el4 = lane >> 2;
    const int wmblk = (warp & 1) * 2;          // 2 m-blocks (32 rows) per warp
    const int wn = (warp >> 1) * 32;           // 32 cols per warp

    int base = 0;
    for (int d = 0; d < NDIAG; ++d) {
        const int l0 = (d > RDIM - 1) ? d - (RDIM - 1) : 0;
        const int l1 = (d < LDIM - 1) ? d : LDIM - 1;
        const int nc = l1 - l0 + 1;
        const int Td = 4 * nc;
        int t0 = cta - (base % ncta);
        if (t0 < 0) t0 += ncta;

        for (int t = t0; t < Td; t += ncta) {
            if (t < nc * 2) {
                // ================= A mega-tile: all 7 n-chunks =============
                const int ci = t >> 1, hb = t & 1;
                const int l = l0 + ci, rr = d - l;
                const int b0 = hb * 64;

                if (tid < 3) {
                    volatile unsigned* f = 0;
                    if (tid == 0)      { if (rr > 0) f = &g_hflag[l][rr - 1][hb]; }
                    else if (tid == 1) { if (l > 0)  f = &g_hflag[l - 1][rr][hb]; }
                    else               { if (l > 0 && rr > 0) f = &g_hflag[l - 1][rr - 1][hb]; }
                    if (f) {
                        while (*f == 0u) __nanosleep(40);
                        __threadfence();
                    }
                }
                __syncthreads();

                const float* htop  = (l > 0)           ? &g_hfull[l - 1][rr][0][0]     : (const float*)0;
                const float* hleft = (rr > 0)          ? &g_hfull[l][rr - 1][0][0]     : (const float*)0;
                const float* hdiag = (l > 0 && rr > 0) ? &g_hfull[l - 1][rr - 1][0][0] : (const float*)0;

                // vectorized fragment build: one task = 4 uint4 groups
                for (int idx = tid; idx < 4 * KB * 8; idx += 256) {
                    const int rl4 = idx & 7;
                    const int kb  = (idx >> 3) % KB;
                    const int mb  = (idx >> 3) / KB;
                    const int blo = b0 + mb * 16 + rl4;
                    const int k0  = kb * 8;
                    uint4 g0, g1, g2, g3;
                    if (k0 < 384) {
                        const float* src; int kk;
                        if (k0 < 128)      { src = htop;  kk = k0; }
                        else if (k0 < 256) { src = hleft; kk = k0 - 128; }
                        else               { src = hdiag; kk = k0 - 256; }
                        if (src) {
                            const float4 lo0 = __ldcg((const float4*)(src + blo * UD + kk));
                            const float4 lo1 = __ldcg((const float4*)(src + blo * UD + kk + 4));
                            const float4 hi0 = __ldcg((const float4*)(src + (blo + 8) * UD + kk));
                            const float4 hi1 = __ldcg((const float4*)(src + (blo + 8) * UD + kk + 4));
                            g0 = make_uint4(f2tf(lo0.x), f2tf(hi0.x), f2tf(lo1.x), f2tf(hi1.x));
                            g1 = make_uint4(f2tf(lo0.y), f2tf(hi0.y), f2tf(lo1.y), f2tf(hi1.y));
                            g2 = make_uint4(f2tf(lo0.z), f2tf(hi0.z), f2tf(lo1.z), f2tf(hi1.z));
                            g3 = make_uint4(f2tf(lo0.w), f2tf(hi0.w), f2tf(lo1.w), f2tf(hi1.w));
                        } else {
                            g0 = g1 = g2 = g3 = make_uint4(0u, 0u, 0u, 0u);
                        }
                    } else {
                        const int c0 = k0 - 384;
                        const uint4 lo0 = *(const uint4*)&g_sT[l][rr][blo][c0];
                        const uint4 lo1 = *(const uint4*)&g_sT[l][rr][blo][c0 + 4];
                        const uint4 hi0 = *(const uint4*)&g_sT[l][rr][blo + 8][c0];
                        const uint4 hi1 = *(const uint4*)&g_sT[l][rr][blo + 8][c0 + 4];
                        g0 = make_uint4(lo0.x, hi0.x, lo1.x, hi1.x);
                        g1 = make_uint4(lo0.y, hi0.y, lo1.y, hi1.y);
                        g2 = make_uint4(lo0.z, hi0.z, lo1.z, hi1.z);
                        g3 = make_uint4(lo0.w, hi0.w, lo1.w, hi1.w);
                    }
                    uint4* dst = (uint4*)(smem + ((mb * KB + kb) * 32 + rl4 * 4) * 4);
                    dst[0] = g0; dst[1] = g1; dst[2] = g2; dst[3] = g3;
                }
                __syncthreads();

                float* lgb = &g_logits[l][0][0];
#pragma unroll 1
                for (int nch = 0; nch < 7; ++nch) {
                    const int jblk0 = nch * 16 + (wn >> 3);
                    float acc[2][4][4];
#pragma unroll
                    for (int mt = 0; mt < 2; ++mt)
#pragma unroll
                        for (int nt = 0; nt < 4; ++nt)
#pragma unroll
                            for (int i = 0; i < 4; ++i) acc[mt][nt][i] = 0.f;
                    uint2 cur[4];
#pragma unroll
                    for (int nt = 0; nt < 4; ++nt)
                        cur[nt] = __ldcg((const uint2*)&g_wpack[jblk0 + nt][0][lane][0]);
#pragma unroll 4
                    for (int kblk = 0; kblk < KB; ++kblk) {
                        uint2 nxt[4];
#pragma unroll
                        for (int nt = 0; nt < 4; ++nt)
                            nxt[nt] = __ldcg((const uint2*)&g_wpack[jblk0 + nt][kblk + 1][lane][0]);
                        uint4 av[2];
#pragma unroll
                        for (int mt = 0; mt < 2; ++mt)
                            av[mt] = *(const uint4*)(smem + (((wmblk + mt) * KB + kblk) * 32 + lane) * 4);
#pragma unroll
                        for (int mt = 0; mt < 2; ++mt)
#pragma unroll
                            for (int nt = 0; nt < 4; ++nt)
                                mma8(acc[mt][nt], av[mt], cur[nt]);
#pragma unroll
                        for (int nt = 0; nt < 4; ++nt) cur[nt] = nxt[nt];
                    }
#pragma unroll
                    for (int nt = 0; nt < 4; ++nt) {
                        const int col = nch * 128 + wn + nt * 8 + (lane & 3) * 2;
                        float bb0, bb1;
                        if (col < 384) { bb0 = br[col];       bb1 = br[col + 1]; }
                        else           { bb0 = bz[col - 384]; bb1 = bz[col - 383]; }
#pragma unroll
                        for (int mt = 0; mt < 2; ++mt) {
                            const int row = b0 + (wmblk + mt) * 16 + el4;
                            __stcg((float2*)(lgb + row * NOUT + col),
                                   make_float2(acc[mt][nt][0] + bb0, acc[mt][nt][1] + bb1));
                            __stcg((float2*)(lgb + (row + 8) * NOUT + col),
                                   make_float2(acc[mt][nt][2] + bb0, acc[mt][nt][3] + bb1));
                        }
                    }
                }
                __threadfence();
                __syncthreads();
                if (tid == 0) atomicAdd(&g_lcnt[l][hb], 1u);
            } else {
                // ======================= B tile ============================
                const int u2 = t - nc * 2;
                const int ci = u2 >> 1, hb = u2 & 1;
                const int l = l0 + ci, rr = d - l;
                const int b0 = hb * 64;
                const unsigned expected = (unsigned)(rr + 1);

                if (tid == 0) {
                    volatile unsigned* c = &g_lcnt[l][hb];
                    while (*c < expected) __nanosleep(40);
                    __threadfence();
                }
                __syncthreads();

                const float* hl = (rr > 0)          ? &g_hfull[l][rr - 1][0][0]     : (const float*)0;
                const float* ht = (l > 0)           ? &g_hfull[l - 1][rr][0][0]     : (const float*)0;
                const float* hd = (l > 0 && rr > 0) ? &g_hfull[l - 1][rr - 1][0][0] : (const float*)0;
                const float* lgb = &g_logits[l][0][0];

                for (int idx = tid; idx < 4 * KB * 8; idx += 256) {
                    const int rl4 = idx & 7;
                    const int kb  = (idx >> 3) % KB;
                    const int mb  = (idx >> 3) / KB;
                    const int blo = b0 + mb * 16 + rl4;
                    const int k0  = kb * 8;
                    uint4 g0, g1, g2, g3;
                    if (k0 < 384) {
                        const float* hsrc; int kk;
                        if (k0 < 128)      { hsrc = hl; kk = k0; }
                        else if (k0 < 256) { hsrc = ht; kk = k0 - 128; }
                        else               { hsrc = hd; kk = k0 - 256; }
                        const float4 la0 = __ldcg((const float4*)(lgb + blo * NOUT + k0));
                        const float4 la1 = __ldcg((const float4*)(lgb + blo * NOUT + k0 + 4));
                        const float4 lb0 = __ldcg((const float4*)(lgb + (blo + 8) * NOUT + k0));
                        const float4 lb1 = __ldcg((const float4*)(lgb + (blo + 8) * NOUT + k0 + 4));
                        float4 ha0, ha1, hb0_, hb1_;
                        if (hsrc) {
                            ha0  = __ldcg((const float4*)(hsrc + blo * UD + kk));
                            ha1  = __ldcg((const float4*)(hsrc + blo * UD + kk + 4));
                            hb0_ = __ldcg((const float4*)(hsrc + (blo + 8) * UD + kk));
                            hb1_ = __ldcg((const float4*)(hsrc + (blo + 8) * UD + kk + 4));
                        } else {
                            ha0 = ha1 = hb0_ = hb1_ = make_float4(0.f, 0.f, 0.f, 0.f);
                        }
                        g0 = make_uint4(f2tf(ha0.x / (1.f + __expf(-la0.x))),
                                        f2tf(hb0_.x / (1.f + __expf(-lb0.x))),
                                        f2tf(ha1.x / (1.f + __expf(-la1.x))),
                                        f2tf(hb1_.x / (1.f + __expf(-lb1.x))));
                        g1 = make_uint4(f2tf(ha0.y / (1.f + __expf(-la0.y))),
                                        f2tf(hb0_.y / (1.f + __expf(-lb0.y))),
                                        f2tf(ha1.y / (1.f + __expf(-la1.y))),
                                        f2tf(hb1_.y / (1.f + __expf(-lb1.y))));
                        g2 = make_uint4(f2tf(ha0.z / (1.f + __expf(-la0.z))),
                                        f2tf(hb0_.z / (1.f + __expf(-lb0.z))),
                                        f2tf(ha1.z / (1.f + __expf(-la1.z))),
                                        f2tf(hb1_.z / (1.f + __expf(-lb1.z))));
                        g3 = make_uint4(f2tf(ha0.w / (1.f + __expf(-la0.w))),
                                        f2tf(hb0_.w / (1.f + __expf(-lb0.w))),
                                        f2tf(ha1.w / (1.f + __expf(-la1.w))),
                                        f2tf(hb1_.w / (1.f + __expf(-lb1.w))));
                    } else {
                        const int c0 = k0 - 384;
                        const uint4 lo0 = *(const uint4*)&g_sT[l][rr][blo][c0];
                        const uint4 lo1 = *(const uint4*)&g_sT[l][rr][blo][c0 + 4];
                        const uint4 hi0 = *(const uint4*)&g_sT[l][rr][blo + 8][c0];
                        const uint4 hi1 = *(const uint4*)&g_sT[l][rr][blo + 8][c0 + 4];
                        g0 = make_uint4(lo0.x, hi0.x, lo1.x, hi1.x);
                        g1 = make_uint4(lo0.y, hi0.y, lo1.y, hi1.y);
                        g2 = make_uint4(lo0.z, hi0.z, lo1.z, hi1.z);
                        g3 = make_uint4(lo0.w, hi0.w, lo1.w, hi1.w);
                    }
                    uint4* dst = (uint4*)(smem + ((mb * KB + kb) * 32 + rl4 * 4) * 4);
                    dst[0] = g0; dst[1] = g1; dst[2] = g2; dst[3] = g3;
                }
                __syncthreads();

                const int jblk0 = 112 + (wn >> 3);
                float acc[2][4][4];
#pragma unroll
                for (int mt = 0; mt < 2; ++mt)
#pragma unroll
                    for (int nt = 0; nt < 4; ++nt)
#pragma unroll
                        for (int i = 0; i < 4; ++i) acc[mt][nt][i] = 0.f;
                uint2 cur[4];
#pragma unroll
                for (int nt = 0; nt < 4; ++nt)
                    cur[nt] = __ldcg((const uint2*)&g_wpack[jblk0 + nt][0][lane][0]);
#pragma unroll 4
                for (int kblk = 0; kblk < KB; ++kblk) {
                    uint2 nxt[4];
#pragma unroll
                    for (int nt = 0; nt < 4; ++nt)
                        nxt[nt] = __ldcg((const uint2*)&g_wpack[jblk0 + nt][kblk + 1][lane][0]);
                    uint4 av[2];
#pragma unroll
                    for (int mt = 0; mt < 2; ++mt)
                        av[mt] = *(const uint4*)(smem + (((wmblk + mt) * KB + kblk) * 32 + lane) * 4);
#pragma unroll
                    for (int mt = 0; mt < 2; ++mt)
#pragma unroll
                        for (int nt = 0; nt < 4; ++nt)
                            mma8(acc[mt][nt], av[mt], cur[nt]);
#pragma unroll
                    for (int nt = 0; nt < 4; ++nt) cur[nt] = nxt[nt];
                }
                __syncthreads();

                float* hmix_s = (float*)smem;
                float* zi_s = hmix_s + 64 * 128;
                for (int idx = tid; idx < 64 * 128; idx += 256) {
                    const int bl = idx >> 7, u = idx & 127;
                    const int b = b0 + bl;
                    const float* zp = lgb + b * NOUT + 384 + u;
                    const float z0 = __ldcg(zp), z1 = __ldcg(zp + 128);
                    const float z2 = __ldcg(zp + 256), z3 = __ldcg(zp + 384);
                    const float m = fmaxf(fmaxf(z0, z1), fmaxf(z2, z3));
                    const float e0 = __expf(z0 - m), e1 = __expf(z1 - m);
                    const float e2 = __expf(z2 - m), e3 = __expf(z3 - m);
                    const float inv = 1.f / (e0 + e1 + e2 + e3);
                    const float hlv = hl ? __ldcg(hl + b * UD + u) : 0.f;
                    const float htv = ht ? __ldcg(ht + b * UD + u) : 0.f;
                    const float hdv = hd ? __ldcg(hd + b * UD + u) : 0.f;
                    hmix_s[idx] = (e1 * hlv + e2 * htv + e3 * hdv) * inv;
                    zi_s[idx]   = e0 * inv;
                }
                __syncthreads();

                float* hout = &g_hfull[l][rr][0][0];
#pragma unroll
                for (int nt = 0; nt < 4; ++nt) {
                    const int u0 = wn + nt * 8 + (lane & 3) * 2;
                    const float2 bj = *(const float2*)(bij + u0);
#pragma unroll
                    for (int mt = 0; mt < 2; ++mt) {
                        const int rl = (wmblk + mt) * 16 + el4;
#pragma unroll
                        for (int hr = 0; hr < 2; ++hr) {
                            const int rloc = rl + hr * 8;
                            const int b = b0 + rloc;
                            const float hh0 = tanhf(acc[mt][nt][hr * 2 + 0] + bj.x);
                            const float hh1 = tanhf(acc[mt][nt][hr * 2 + 1] + bj.y);
                            const float2 hm = *(const float2*)(hmix_s + rloc * 128 + u0);
                            const float2 zi = *(const float2*)(zi_s + rloc * 128 + u0);
                            const float h0 = hm.x + zi.x * hh0;
                            const float h1 = hm.y + zi.y * hh1;
                            __stcg((float2*)(hout + b * UD + u0), make_float2(h0, h1));
                            if (d == NDIAG - 1)
                                *(float2*)(out + b * UD + u0) = make_float2(h0, h1);
                        }
                    }
                }
                __threadfence();
                __syncthreads();
                if (tid == 0) *(volatile unsigned*)&g_hflag[l][rr][hb] = 1u;
            }
        }
        base += Td;
    }
}

// ---------------------------------------------------------------------------
extern "C" void kernel_launch(void* const* d_in, const int* in_sizes, int n_in,
                              void* d_out, int out_size)
{
    const float* inputs = (const float*)d_in[0];
    const float* Wr     = (const float*)d_in[1];
    const float* br     = (const float*)d_in[2];
    const float* Wz     = (const float*)d_in[3];
    const float* bz     = (const float*)d_in[4];
    const float* Wij    = (const float*)d_in[5];
    const float* bij    = (const float*)d_in[6];
    const float* WU     = (const float*)d_in[7];
    float* out = (float*)d_out;

    const int SMEM = 4 * KB * 32 * 4 * (int)sizeof(unsigned);  // 106496 B
    cudaFuncSetAttribute(spatial_gru_flow,
                         cudaFuncAttributeMaxDynamicSharedMemorySize, SMEM);
    int dev = 0;
    cudaGetDevice(&dev);
    int nsm = 0;
    cudaDeviceGetAttribute(&nsm, cudaDevAttrMultiProcessorCount, dev);
    int occ = 0;
    cudaOccupancyMaxActiveBlocksPerMultiprocessor(&occ, spatial_gru_flow, 256, SMEM);
    if (occ < 1) occ = 1;
    const int ncta = nsm * occ;   // grid == resident CTAs (deadlock-free dataflow)

    spatial_gru_flow<<<ncta, 256, SMEM>>>(inputs, Wr, br, Wz, bz, Wij, bij,
                                          WU, out, ncta);
}

// round 5
// speedup vs baseline: 1.3545x; 1.3545x over previous
#include <cuda_runtime.h>

#define LDIM 80
#define RDIM 80
#define BATCH 128
#define UD 128
#define CD 32
#define DD 416
#define NDIAG 159
#define KB 52
#define KBP 54
#define QW (4 * KB * 32 * 4)   // words per fragment-packed 64x416 tile

// Full h storage for every cell (no rotation: pipelining-safe).
__device__ float    g_hfull[LDIM][RDIM][BATCH][UD];      // 419 MB
// Pre-transposed tf32 inputs: (l, r, b, c).
__device__ unsigned g_sT[LDIM][RDIM][BATCH][CD];         // 104 MB
// Fragment-packed tf32 weights:
//   jblk   0..47  : Wr rows 0..383
//   jblk  48..111 : Wz interleaved: packed col jz -> Wz row (jz&3)*128 + (jz>>2)
//   jblk 112..127 : [WU | Wij] rows u = (jblk-112)*8+...
__device__ unsigned g_wpack[128][KBP][32][2];
// Dataflow flags (reset every run).
__device__ unsigned g_hflag[LDIM][RDIM][2];
__device__ unsigned g_count;
__device__ unsigned g_sense;

__device__ __forceinline__ unsigned f2tf(float x) {
    unsigned u;
    asm("cvt.rna.tf32.f32 %0, %1;" : "=r"(u) : "f"(x));
    return u;
}

__device__ __forceinline__ void mma8(float* c, const uint4& a, const uint2& b) {
    asm volatile(
        "mma.sync.aligned.m16n8k8.row.col.f32.tf32.tf32.f32 "
        "{%0,%1,%2,%3}, {%4,%5,%6,%7}, {%8,%9}, {%0,%1,%2,%3};\n"
        : "+f"(c[0]), "+f"(c[1]), "+f"(c[2]), "+f"(c[3])
        : "r"(a.x), "r"(a.y), "r"(a.z), "r"(a.w), "r"(b.x), "r"(b.y));
}

// word index of element (local row, k) in a fragment-packed tile
__device__ __forceinline__ int qaddr(int row, int k) {
    const int mb = row >> 4, rl = row & 15;
    const int rl4 = rl & 7, hi = rl >> 3;
    const int kb = k >> 3, kh = (k >> 2) & 1, kc = k & 3;
    return ((mb * KB + kb) * 32 + rl4 * 4 + kc) * 4 + hi + 2 * kh;
}

__device__ __forceinline__ void gbar(int ncta, unsigned& sense) {
    __syncthreads();
    if (threadIdx.x == 0) {
        __threadfence();
        unsigned arrived = atomicAdd(&g_count, 1u) + 1u;
        if (arrived == (unsigned)ncta) {
            g_count = 0u;
            __threadfence();
            atomicAdd(&g_sense, 1u);
        } else {
            while ((int)(*(volatile unsigned*)&g_sense - (sense + 1u)) < 0) {
                __nanosleep(64);
            }
        }
    }
    sense += 1u;
    __syncthreads();
}

__global__ __launch_bounds__(512, 1) void spatial_gru_fused(
    const float* __restrict__ inputs, const float* __restrict__ Wr,
    const float* __restrict__ br, const float* __restrict__ Wz,
    const float* __restrict__ bz, const float* __restrict__ Wij,
    const float* __restrict__ bij, const float* __restrict__ WU,
    float* __restrict__ out, int ncta)
{
    extern __shared__ unsigned smem[];
    unsigned* qs = smem;
    unsigned* a2 = smem + QW;
    const int tid = threadIdx.x;
    const int cta = blockIdx.x;
    const int gtid = cta * 512 + tid;
    const int gstride = ncta * 512;
    unsigned sense = *(volatile unsigned*)&g_sense;

    // ---------------- stage 0: pack weights, transpose s, reset flags ------
    for (int idx = gtid; idx < 128 * KB * 32; idx += gstride) {
        const int lane = idx & 31;
        const int kblk = (idx >> 5) % KB;
        const int jblk = (idx >> 5) / KB;
        const int jp = jblk * 8 + (lane >> 2);
        const int k = kblk * 8 + (lane & 3);
        float v0, v1;
        if (jblk < 48) {
            v0 = Wr[jp * DD + k]; v1 = Wr[jp * DD + k + 4];
        } else if (jblk < 112) {
            const int jz = jp - 384;
            const int j = (jz & 3) * 128 + (jz >> 2);
            v0 = Wz[j * DD + k]; v1 = Wz[j * DD + k + 4];
        } else {
            const int u = jp - 896;
            v0 = (k < 384)     ? WU[u * 384 + k]     : Wij[u * 32 + (k - 384)];
            v1 = (k + 4 < 384) ? WU[u * 384 + k + 4] : Wij[u * 32 + (k - 380)];
        }
        g_wpack[jblk][kblk][lane][0] = f2tf(v0);
        g_wpack[jblk][kblk][lane][1] = f2tf(v1);
    }
    // transpose inputs (B,C,L,R) -> tf32 (L,R,B,C)
    for (int idx = gtid; idx < LDIM * RDIM * BATCH * (CD / 4); idx += gstride) {
        const int c4 = idx & 7;
        const int b  = (idx >> 3) & 127;
        const int r  = (idx >> 10) % RDIM;
        const int l  = (idx >> 10) / RDIM;
        const int c  = c4 * 4;
        const float* sp = inputs + (((size_t)b * CD + c) * LDIM + l) * RDIM + r;
        unsigned* dst = &g_sT[l][r][b][c];
        dst[0] = f2tf(sp[0]);
        dst[1] = f2tf(sp[LDIM * RDIM]);
        dst[2] = f2tf(sp[2 * LDIM * RDIM]);
        dst[3] = f2tf(sp[3 * LDIM * RDIM]);
    }
    for (int idx = gtid; idx < LDIM * RDIM * 2; idx += gstride)
        ((unsigned*)g_hflag)[idx] = 0u;
    gbar(ncta, sense);

    const int warp = tid >> 5, lane = tid & 31;
    const int l4 = lane >> 2;
    const int wm = warp >> 3;   // m-half: rows [wm*32, wm*32+32)
    const int wn = warp & 7;    // n-warp index

    int base = 0;
    for (int d = 0; d < NDIAG; ++d) {
        const int l0 = (d > RDIM - 1) ? d - (RDIM - 1) : 0;
        const int l1 = (d < LDIM - 1) ? d : LDIM - 1;
        const int nc = l1 - l0 + 1;
        const int Td = 2 * nc;
        int t0 = cta - (base % ncta);
        if (t0 < 0) t0 += ncta;

        for (int t = t0; t < Td; t += ncta) {
            const int ci = t >> 1, hb = t & 1;
            const int l = l0 + ci, rr = d - l;
            const int b0 = hb * 64;

            // -------- wait for neighbor h flags --------
            if (tid < 3) {
                volatile unsigned* f = 0;
                if (tid == 0)      { if (rr > 0) f = &g_hflag[l][rr - 1][hb]; }
                else if (tid == 1) { if (l > 0)  f = &g_hflag[l - 1][rr][hb]; }
                else               { if (l > 0 && rr > 0) f = &g_hflag[l - 1][rr - 1][hb]; }
                if (f) {
                    while (*f == 0u) __nanosleep(40);
                    __threadfence();
                }
            }
            __syncthreads();

            const float* htop  = (l > 0)           ? &g_hfull[l - 1][rr][0][0]     : (const float*)0;
            const float* hleft = (rr > 0)          ? &g_hfull[l][rr - 1][0][0]     : (const float*)0;
            const float* hdiag = (l > 0 && rr > 0) ? &g_hfull[l - 1][rr - 1][0][0] : (const float*)0;

            // -------- build q fragments (conflict-free STS.128) --------
            for (int idx = tid; idx < 4 * KB * 32; idx += 512) {
                const int kc  = idx & 3;
                const int rl4 = (idx >> 2) & 7;
                const int un  = idx >> 5;
                const int kb  = un % KB;
                const int mb  = un / KB;
                const int blo = b0 + mb * 16 + rl4;
                const int k   = kb * 8 + kc;
                unsigned s0, s1, s2, s3;
                if (kb < 48) {
                    const float* src; int kk;
                    if (k < 128)      { src = htop;  kk = k; }
                    else if (k < 256) { src = hleft; kk = k - 128; }
                    else              { src = hdiag; kk = k - 256; }
                    if (src) {
                        s0 = f2tf(__ldcg(src + blo * UD + kk));
                        s1 = f2tf(__ldcg(src + (blo + 8) * UD + kk));
                        s2 = f2tf(__ldcg(src + blo * UD + kk + 4));
                        s3 = f2tf(__ldcg(src + (blo + 8) * UD + kk + 4));
                    } else { s0 = s1 = s2 = s3 = 0u; }
                } else {
                    const int c = k - 384;
                    s0 = g_sT[l][rr][blo][c];
                    s1 = g_sT[l][rr][blo + 8][c];
                    s2 = g_sT[l][rr][blo][c + 4];
                    s3 = g_sT[l][rr][blo + 8][c + 4];
                }
                *(uint4*)(qs + ((mb * KB + kb) * 32 + rl4 * 4 + kc) * 4) =
                    make_uint4(s0, s1, s2, s3);
            }
            __syncthreads();

            // ================= GEMM1-r: N=384, warp = 2mt x 6 jblk =========
            {
                const int jb = wn * 6;
                float acc[2][6][4];
#pragma unroll
                for (int mt = 0; mt < 2; ++mt)
#pragma unroll
                    for (int nt = 0; nt < 6; ++nt)
#pragma unroll
                        for (int i = 0; i < 4; ++i) acc[mt][nt][i] = 0.f;
                uint2 wb[2][6];
#pragma unroll
                for (int nt = 0; nt < 6; ++nt) {
                    wb[0][nt] = __ldcg((const uint2*)&g_wpack[jb + nt][0][lane][0]);
                    wb[1][nt] = __ldcg((const uint2*)&g_wpack[jb + nt][1][lane][0]);
                }
#pragma unroll 2
                for (int kb = 0; kb < KB; ++kb) {
                    const int par = kb & 1;
                    uint4 av[2];
#pragma unroll
                    for (int mt = 0; mt < 2; ++mt)
                        av[mt] = *(const uint4*)(qs + (((wm * 2 + mt) * KB + kb) * 32 + lane) * 4);
#pragma unroll
                    for (int mt = 0; mt < 2; ++mt)
#pragma unroll
                        for (int nt = 0; nt < 6; ++nt)
                            mma8(acc[mt][nt], av[mt], wb[par][nt]);
#pragma unroll
                    for (int nt = 0; nt < 6; ++nt)
                        wb[par][nt] = __ldcg((const uint2*)&g_wpack[jb + nt][kb + 2][lane][0]);
                }
                // sigmoid(r) * h  -> A2 fragments (+ bias)
#pragma unroll
                for (int nt = 0; nt < 6; ++nt) {
                    const int col0 = (jb + nt) * 8 + (lane & 3) * 2;
                    const float b0r = br[col0], b1r = br[col0 + 1];
                    const int qc0 = (col0 < 128) ? col0 + 128
                                  : (col0 < 256) ? col0 - 128 : col0;
#pragma unroll
                    for (int mt = 0; mt < 2; ++mt) {
                        const int rowa = wm * 32 + mt * 16 + l4;
#pragma unroll
                        for (int rs = 0; rs < 2; ++rs) {
                            const int row = rowa + rs * 8;
#pragma unroll
                            for (int cc = 0; cc < 2; ++cc) {
                                const float pre = acc[mt][nt][rs * 2 + cc] + (cc ? b1r : b0r);
                                const float sg = 1.f / (1.f + __expf(-pre));
                                const float hv = *(const float*)(qs + qaddr(row, qc0 + cc));
                                a2[qaddr(row, col0 + cc)] = f2tf(sg * hv);
                            }
                        }
                    }
                }
            }
            // copy s kblks (48..51) from q into A2
            {
                const int lane2 = tid & 31;
                const int kb2 = 48 + ((tid >> 5) & 3);
                const int mb2 = tid >> 7;
                const int off = (mb2 * KB + kb2) * 32 + lane2;
                ((uint4*)a2)[off] = ((const uint4*)qs)[off];
            }

            // ================= GEMM1-z: N=512 interleaved, 2mt x 8 jblk ====
            float accz[2][8][4];
            {
                const int jb = 48 + wn * 8;
#pragma unroll
                for (int mt = 0; mt < 2; ++mt)
#pragma unroll
                    for (int nt = 0; nt < 8; ++nt)
#pragma unroll
                        for (int i = 0; i < 4; ++i) accz[mt][nt][i] = 0.f;
                uint2 wb[2][8];
#pragma unroll
                for (int nt = 0; nt < 8; ++nt) {
                    wb[0][nt] = __ldcg((const uint2*)&g_wpack[jb + nt][0][lane][0]);
                    wb[1][nt] = __ldcg((const uint2*)&g_wpack[jb + nt][1][lane][0]);
                }
#pragma unroll 2
                for (int kb = 0; kb < KB; ++kb) {
                    const int par = kb & 1;
                    uint4 av[2];
#pragma unroll
                    for (int mt = 0; mt < 2; ++mt)
                        av[mt] = *(const uint4*)(qs + (((wm * 2 + mt) * KB + kb) * 32 + lane) * 4);
#pragma unroll
                    for (int mt = 0; mt < 2; ++mt)
#pragma unroll
                        for (int nt = 0; nt < 8; ++nt)
                            mma8(accz[mt][nt], av[mt], wb[par][nt]);
#pragma unroll
                    for (int nt = 0; nt < 8; ++nt)
                        wb[par][nt] = __ldcg((const uint2*)&g_wpack[jb + nt][kb + 2][lane][0]);
                }
                // register softmax over 4 z-groups (partner = lane^1), hmix
#pragma unroll
                for (int nt = 0; nt < 8; ++nt) {
                    const int pcol = (jb + nt) * 8 - 384 + (lane & 3) * 2;
                    const int u = pcol >> 2;
                    const int gb = pcol & 3;                 // 0 (even) or 2 (odd)
                    const bool ev = (gb == 0);
                    const float bz0 = bz[gb * 128 + u];
                    const float bz1 = bz[(gb + 1) * 128 + u];
#pragma unroll
                    for (int mt = 0; mt < 2; ++mt) {
                        const int rowa = wm * 32 + mt * 16 + l4;
                        float zi2[2], hm2[2];
#pragma unroll
                        for (int rs = 0; rs < 2; ++rs) {
                            const int row = rowa + rs * 8;
                            const float v0 = accz[mt][nt][rs * 2 + 0] + bz0;
                            const float v1 = accz[mt][nt][rs * 2 + 1] + bz1;
                            float m = fmaxf(v0, v1);
                            m = fmaxf(m, __shfl_xor_sync(0xffffffffu, m, 1));
                            const float e0 = __expf(v0 - m), e1 = __expf(v1 - m);
                            float s = e0 + e1;
                            s += __shfl_xor_sync(0xffffffffu, s, 1);
                            const float inv = 1.f / s;
                            float part;
                            if (ev) {
                                const float hlv = *(const float*)(qs + qaddr(row, 128 + u));
                                part = e1 * hlv;
                            } else {
                                const float htv = *(const float*)(qs + qaddr(row, u));
                                const float hdv = *(const float*)(qs + qaddr(row, 256 + u));
                                part = e0 * htv + e1 * hdv;
                            }
                            const float hm = (part + __shfl_xor_sync(0xffffffffu, part, 1)) * inv;
                            zi2[rs] = e0 * inv;   // meaningful on even lanes
                            hm2[rs] = hm;
                        }
                        accz[mt][nt][0] = zi2[0]; accz[mt][nt][1] = hm2[0];
                        accz[mt][nt][2] = zi2[1]; accz[mt][nt][3] = hm2[1];
                    }
                }
            }
            __syncthreads();   // all q/A2 reads+writes done

            // stash zi/hmix into (dead) q region
            float* hmix_s = (float*)smem;
            float* zi_s   = hmix_s + 64 * 128;
            if ((lane & 1) == 0) {
                const int jb = 48 + wn * 8;
#pragma unroll
                for (int nt = 0; nt < 8; ++nt) {
                    const int pcol = (jb + nt) * 8 - 384 + (lane & 3) * 2;
                    const int u = pcol >> 2;
#pragma unroll
                    for (int mt = 0; mt < 2; ++mt) {
                        const int rowa = wm * 32 + mt * 16 + l4;
                        zi_s[rowa * 128 + u]         = accz[mt][nt][0];
                        hmix_s[rowa * 128 + u]       = accz[mt][nt][1];
                        zi_s[(rowa + 8) * 128 + u]   = accz[mt][nt][2];
                        hmix_s[(rowa + 8) * 128 + u] = accz[mt][nt][3];
                    }
                }
            }
            __syncthreads();

            // ================= GEMM2: N=128, warp = 2mt x 2 jblk ===========
            {
                const int jb = 112 + wn * 2;
                float acc2[2][2][4];
#pragma unroll
                for (int mt = 0; mt < 2; ++mt)
#pragma unroll
                    for (int nt = 0; nt < 2; ++nt)
#pragma unroll
                        for (int i = 0; i < 4; ++i) acc2[mt][nt][i] = 0.f;
                uint2 wb[2][2];
#pragma unroll
                for (int nt = 0; nt < 2; ++nt) {
                    wb[0][nt] = __ldcg((const uint2*)&g_wpack[jb + nt][0][lane][0]);
                    wb[1][nt] = __ldcg((const uint2*)&g_wpack[jb + nt][1][lane][0]);
                }
#pragma unroll 2
                for (int kb = 0; kb < KB; ++kb) {
                    const int par = kb & 1;
                    uint4 av[2];
#pragma unroll
                    for (int mt = 0; mt < 2; ++mt)
                        av[mt] = *(const uint4*)(a2 + (((wm * 2 + mt) * KB + kb) * 32 + lane) * 4);
#pragma unroll
                    for (int mt = 0; mt < 2; ++mt)
#pragma unroll
                        for (int nt = 0; nt < 2; ++nt)
                            mma8(acc2[mt][nt], av[mt], wb[par][nt]);
#pragma unroll
                    for (int nt = 0; nt < 2; ++nt)
                        wb[par][nt] = __ldcg((const uint2*)&g_wpack[jb + nt][kb + 2][lane][0]);
                }
                // h = hmix + zi * tanh(ghat + bij)
                float* hout = &g_hfull[l][rr][0][0];
#pragma unroll
                for (int nt = 0; nt < 2; ++nt) {
                    const int u0 = (wn * 2 + nt) * 8 + (lane & 3) * 2;
                    const float2 bj = *(const float2*)(bij + u0);
#pragma unroll
                    for (int mt = 0; mt < 2; ++mt) {
                        const int rowa = wm * 32 + mt * 16 + l4;
#pragma unroll
                        for (int rs = 0; rs < 2; ++rs) {
                            const int row = rowa + rs * 8;
                            const int b = b0 + row;
                            const float h0 = hmix_s[row * 128 + u0] +
                                zi_s[row * 128 + u0] *
                                tanhf(acc2[mt][nt][rs * 2 + 0] + bj.x);
                            const float h1 = hmix_s[row * 128 + u0 + 1] +
                                zi_s[row * 128 + u0 + 1] *
                                tanhf(acc2[mt][nt][rs * 2 + 1] + bj.y);
                            __stcg((float2*)(hout + b * UD + u0), make_float2(h0, h1));
                            if (d == NDIAG - 1)
                                *(float2*)(out + b * UD + u0) = make_float2(h0, h1);
                        }
                    }
                }
            }
            __threadfence();
            __syncthreads();
            if (tid == 0) *(volatile unsigned*)&g_hflag[l][rr][hb] = 1u;
        }
        base += Td;
    }
}

// ---------------------------------------------------------------------------
extern "C" void kernel_launch(void* const* d_in, const int* in_sizes, int n_in,
                              void* d_out, int out_size)
{
    const float* inputs = (const float*)d_in[0];
    const float* Wr     = (const float*)d_in[1];
    const float* br     = (const float*)d_in[2];
    const float* Wz     = (const float*)d_in[3];
    const float* bz     = (const float*)d_in[4];
    const float* Wij    = (const float*)d_in[5];
    const float* bij    = (const float*)d_in[6];
    const float* WU     = (const float*)d_in[7];
    float* out = (float*)d_out;

    const int SMEM = 2 * QW * (int)sizeof(unsigned);   // 212992 B
    cudaFuncSetAttribute(spatial_gru_fused,
                         cudaFuncAttributeMaxDynamicSharedMemorySize, SMEM);
    int dev = 0;
    cudaGetDevice(&dev);
    int nsm = 0;
    cudaDeviceGetAttribute(&nsm, cudaDevAttrMultiProcessorCount, dev);
    const int ncta = nsm;   // 1 CTA/SM; grid == resident CTAs (deadlock-free)

    spatial_gru_fused<<<ncta, 512, SMEM>>>(inputs, Wr, br, Wz, bz, Wij, bij,
                                           WU, out, ncta);
}

// round 9
// speedup vs baseline: 2.3722x; 1.7514x over previous
#include <cuda_runtime.h>
#include <cuda_fp16.h>

#define LDIM 80
#define RDIM 80
#define BATCH 128
#define UD 128
#define CD 32
#define DD 416
#define NDIAG 159
#define KB16 26          // 416 / 16
#define KBW 28           // padded for prefetch
#define QWH (4 * KB16 * 32 * 4)   // uint words per 64x416 fp16 fragment tile

// Fragment-packed fp16 h per (l, r, hb): [4 mb][8 kb][32 lanes] uint4 = 16 KB slab.
__device__ unsigned g_hhalf[LDIM][RDIM][2][4 * 8 * 32 * 4];   // ~210 MB
// fp16 inputs, (l, r, b, c) layout.
__device__ __half   g_sTh[LDIM][RDIM][BATCH][CD];             // ~52 MB
// Fragment-packed fp16 weights: jblk 0..47 Wr; 48..111 Wz interleaved; 112..127 [WU|Wij]
__device__ uint2    g_wph[128][KBW][32];
// Dataflow flags.
__device__ unsigned g_hflag[LDIM][RDIM][2];
__device__ unsigned g_count;
__device__ unsigned g_sense;

__device__ __forceinline__ unsigned packh2(float a, float b) {
    __half2 h = __floats2half2_rn(a, b);
    return *(unsigned*)&h;
}

__device__ __forceinline__ void mma16(float* c, const uint4& a, const uint2& b) {
    asm volatile(
        "mma.sync.aligned.m16n8k16.row.col.f32.f16.f16.f32 "
        "{%0,%1,%2,%3}, {%4,%5,%6,%7}, {%8,%9}, {%0,%1,%2,%3};\n"
        : "+f"(c[0]), "+f"(c[1]), "+f"(c[2]), "+f"(c[3])
        : "r"(a.x), "r"(a.y), "r"(a.z), "r"(a.w), "r"(b.x), "r"(b.y));
}

// word index (4B) of the half2 (col, col+1), col even, in a q/a2 fragment tile
__device__ __forceinline__ int q2addr(int row, int col) {
    const int mb = row >> 4, rho = row & 15;
    const int kb = col >> 4, kap = col & 15;
    return ((mb * KB16 + kb) * 32 + (rho & 7) * 4 + ((kap >> 1) & 3)) * 4 +
           (rho >> 3) + 2 * (kap >> 3);
}
// same for an h slab (8 kb blocks)
__device__ __forceinline__ int h2addr(int row, int col) {
    const int mb = row >> 4, rho = row & 15;
    const int kb = col >> 4, kap = col & 15;
    return ((mb * 8 + kb) * 32 + (rho & 7) * 4 + ((kap >> 1) & 3)) * 4 +
           (rho >> 3) + 2 * (kap >> 3);
}

__device__ __forceinline__ void gbar(int ncta, unsigned& sense) {
    __syncthreads();
    if (threadIdx.x == 0) {
        __threadfence();
        unsigned arrived = atomicAdd(&g_count, 1u) + 1u;
        if (arrived == (unsigned)ncta) {
            g_count = 0u;
            __threadfence();
            atomicAdd(&g_sense, 1u);
        } else {
            while ((int)(*(volatile unsigned*)&g_sense - (sense + 1u)) < 0) {
                __nanosleep(64);
            }
        }
    }
    sense += 1u;
    __syncthreads();
}

__global__ __launch_bounds__(512, 1) void spatial_gru_h16(
    const float* __restrict__ inputs, const float* __restrict__ Wr,
    const float* __restrict__ br, const float* __restrict__ Wz,
    const float* __restrict__ bz, const float* __restrict__ Wij,
    const float* __restrict__ bij, const float* __restrict__ WU,
    float* __restrict__ out, int ncta)
{
    extern __shared__ unsigned smem[];
    unsigned* qs = smem;
    unsigned* a2 = smem + QWH;
    const int tid = threadIdx.x;
    const int cta = blockIdx.x;
    const int gtid = cta * 512 + tid;
    const int gstride = ncta * 512;
    unsigned sense = *(volatile unsigned*)&g_sense;

    // ---------------- stage 0 -------------------------------------------
    // pack weights -> fp16 fragments
    for (int idx = gtid; idx < 128 * KB16 * 32; idx += gstride) {
        const int lane = idx & 31;
        const int kb = (idx >> 5) % KB16;
        const int jblk = (idx >> 5) / KB16;
        const int jp = jblk * 8 + (lane >> 2);
        const int k = kb * 16 + (lane & 3) * 2;
        float w0, w1, w8, w9;
        if (jblk < 48) {
            const float* p = Wr + (size_t)jp * DD + k;
            w0 = p[0]; w1 = p[1]; w8 = p[8]; w9 = p[9];
        } else if (jblk < 112) {
            const int jz = jp - 384;
            const int j = (jz & 3) * 128 + (jz >> 2);
            const float* p = Wz + (size_t)j * DD + k;
            w0 = p[0]; w1 = p[1]; w8 = p[8]; w9 = p[9];
        } else {
            const int u = jp - 896;
            if (k < 384) {
                const float* p = WU + (size_t)u * 384 + k;
                w0 = p[0]; w1 = p[1]; w8 = p[8]; w9 = p[9];
            } else {
                const float* p = Wij + (size_t)u * 32 + (k - 384);
                w0 = p[0]; w1 = p[1]; w8 = p[8]; w9 = p[9];
            }
        }
        g_wph[jblk][kb][lane] = make_uint2(packh2(w0, w1), packh2(w8, w9));
    }
    // transpose inputs (B,C,L,R) -> fp16 (L,R,B,C)
    for (int idx = gtid; idx < BATCH * (CD / 2) * LDIM * (RDIM / 4); idx += gstride) {
        const int r4 = idx % (RDIM / 4);
        int t2 = idx / (RDIM / 4);
        const int l = t2 % LDIM; t2 /= LDIM;
        const int c2 = t2 & 15;
        const int b = t2 >> 4;
        const int c = c2 * 2, r0 = r4 * 4;
        const float* p0 = inputs + (((size_t)b * CD + c) * LDIM + l) * RDIM + r0;
        const float4 x0 = *(const float4*)p0;
        const float4 x1 = *(const float4*)(p0 + LDIM * RDIM);
        *(unsigned*)&g_sTh[l][r0 + 0][b][c] = packh2(x0.x, x1.x);
        *(unsigned*)&g_sTh[l][r0 + 1][b][c] = packh2(x0.y, x1.y);
        *(unsigned*)&g_sTh[l][r0 + 2][b][c] = packh2(x0.z, x1.z);
        *(unsigned*)&g_sTh[l][r0 + 3][b][c] = packh2(x0.w, x1.w);
    }
    for (int idx = gtid; idx < LDIM * RDIM * 2; idx += gstride)
        ((unsigned*)g_hflag)[idx] = 0u;
    gbar(ncta, sense);

    const int warp = tid >> 5, lane = tid & 31;
    const int l4 = lane >> 2;
    const int wm = warp >> 3;   // m-half: local rows [wm*32, wm*32+32)
    const int wn = warp & 7;    // n-warp index

    int base = 0;
    for (int d = 0; d < NDIAG; ++d) {
        const int l0 = (d > RDIM - 1) ? d - (RDIM - 1) : 0;
        const int l1 = (d < LDIM - 1) ? d : LDIM - 1;
        const int nc = l1 - l0 + 1;
        const int Td = 2 * nc;
        int t0 = cta - (base % ncta);
        if (t0 < 0) t0 += ncta;

        for (int t = t0; t < Td; t += ncta) {
            const int ci = t >> 1, hb = t & 1;
            const int l = l0 + ci, rr = d - l;
            const int b0 = hb * 64;

            // -------- wait for neighbor h flags --------
            if (tid < 3) {
                volatile unsigned* f = 0;
                if (tid == 0)      { if (rr > 0) f = &g_hflag[l][rr - 1][hb]; }
                else if (tid == 1) { if (l > 0)  f = &g_hflag[l - 1][rr][hb]; }
                else               { if (l > 0 && rr > 0) f = &g_hflag[l - 1][rr - 1][hb]; }
                if (f) {
                    while (*f == 0u) __nanosleep(40);
                    __threadfence();
                }
            }
            __syncthreads();

            const uint4* ghtop  = (l > 0)  ? (const uint4*)&g_hhalf[l - 1][rr][hb][0] : (const uint4*)0;
            const uint4* ghleft = (rr > 0) ? (const uint4*)&g_hhalf[l][rr - 1][hb][0] : (const uint4*)0;
            const uint4* ghdiag = (l > 0 && rr > 0)
                                 ? (const uint4*)&g_hhalf[l - 1][rr - 1][hb][0] : (const uint4*)0;

            // -------- build q: h regions are direct fragment copies --------
            for (int idx = tid; idx < 3072; idx += 512) {
                const int ln = idx & 31;
                const int kq = (idx >> 5) % 24;
                const int mb = (idx >> 5) / 24;
                const uint4* src;
                if (kq < 8)       src = ghtop;
                else if (kq < 16) src = ghleft;
                else              src = ghdiag;
                uint4 v = make_uint4(0u, 0u, 0u, 0u);
                if (src) v = src[(mb * 8 + (kq & 7)) * 32 + ln];
                *(uint4*)(qs + ((mb * KB16 + kq) * 32 + ln) * 4) = v;
            }
            // s region (q kb 24,25)
            if (tid < 256) {
                const int ln = tid & 31;
                const int kb2 = (tid >> 5) & 1;
                const int mb = tid >> 6;
                const int rl4 = ln >> 2, klane = ln & 3;
                const int row = b0 + mb * 16 + rl4;
                const int c0 = kb2 * 16 + klane * 2;
                const __half* s0 = &g_sTh[l][rr][row][0];
                const __half* s1 = &g_sTh[l][rr][row + 8][0];
                uint4 v;
                v.x = *(const unsigned*)(s0 + c0);
                v.y = *(const unsigned*)(s1 + c0);
                v.z = *(const unsigned*)(s0 + c0 + 8);
                v.w = *(const unsigned*)(s1 + c0 + 8);
                *(uint4*)(qs + ((mb * KB16 + 24 + kb2) * 32 + ln) * 4) = v;
            }
            __syncthreads();

            // ================= GEMM1-r: N=384, warp = 2mt x 6 jblk =========
            {
                const int jb = wn * 6;
                float acc[2][6][4];
#pragma unroll
                for (int mt = 0; mt < 2; ++mt)
#pragma unroll
                    for (int nt = 0; nt < 6; ++nt)
#pragma unroll
                        for (int i = 0; i < 4; ++i) acc[mt][nt][i] = 0.f;
                uint2 wb[2][6];
#pragma unroll
                for (int nt = 0; nt < 6; ++nt) {
                    wb[0][nt] = g_wph[jb + nt][0][lane];
                    wb[1][nt] = g_wph[jb + nt][1][lane];
                }
#pragma unroll 2
                for (int kb = 0; kb < KB16; ++kb) {
                    const int par = kb & 1;
                    uint4 av[2];
#pragma unroll
                    for (int mt = 0; mt < 2; ++mt)
                        av[mt] = *(const uint4*)(qs + (((wm * 2 + mt) * KB16 + kb) * 32 + lane) * 4);
#pragma unroll
                    for (int mt = 0; mt < 2; ++mt)
#pragma unroll
                        for (int nt = 0; nt < 6; ++nt)
                            mma16(acc[mt][nt], av[mt], wb[par][nt]);
#pragma unroll
                    for (int nt = 0; nt < 6; ++nt)
                        wb[par][nt] = g_wph[jb + nt][kb + 2][lane];
                }
                // a2 = sigmoid(r + br) * h (block-swapped source)
#pragma unroll
                for (int nt = 0; nt < 6; ++nt) {
                    const int col0 = (jb + nt) * 8 + (lane & 3) * 2;
                    const float b0r = br[col0], b1r = br[col0 + 1];
                    const int qc0 = (col0 < 128) ? col0 + 128
                                  : (col0 < 256) ? col0 - 128 : col0;
#pragma unroll
                    for (int mt = 0; mt < 2; ++mt) {
#pragma unroll
                        for (int rs = 0; rs < 2; ++rs) {
                            const int rowl = wm * 32 + mt * 16 + l4 + rs * 8;
                            const unsigned hv = qs[q2addr(rowl, qc0)];
                            const __half2 hh = *(const __half2*)&hv;
                            const float p0 = acc[mt][nt][rs * 2 + 0] + b0r;
                            const float p1 = acc[mt][nt][rs * 2 + 1] + b1r;
                            const float v0 = __low2float(hh) / (1.f + __expf(-p0));
                            const float v1 = __high2float(hh) / (1.f + __expf(-p1));
                            a2[q2addr(rowl, col0)] = packh2(v0, v1);
                        }
                    }
                }
            }
            // copy s blocks q -> a2
            if (tid < 256) {
                const int ln = tid & 31;
                const int kb2 = (tid >> 5) & 1;
                const int mb = tid >> 6;
                const int off = (mb * KB16 + 24 + kb2) * 32 + ln;
                ((uint4*)a2)[off] = ((const uint4*)qs)[off];
            }

            // ================= GEMM1-z: N=512 interleaved, 2mt x 8 jblk ====
            float accz[2][8][4];
            {
                const int jb = 48 + wn * 8;
#pragma unroll
                for (int mt = 0; mt < 2; ++mt)
#pragma unroll
                    for (int nt = 0; nt < 8; ++nt)
#pragma unroll
                        for (int i = 0; i < 4; ++i) accz[mt][nt][i] = 0.f;
                uint2 wb[2][8];
#pragma unroll
                for (int nt = 0; nt < 8; ++nt) {
                    wb[0][nt] = g_wph[jb + nt][0][lane];
                    wb[1][nt] = g_wph[jb + nt][1][lane];
                }
#pragma unroll 2
                for (int kb = 0; kb < KB16; ++kb) {
                    const int par = kb & 1;
                    uint4 av[2];
#pragma unroll
                    for (int mt = 0; mt < 2; ++mt)
                        av[mt] = *(const uint4*)(qs + (((wm * 2 + mt) * KB16 + kb) * 32 + lane) * 4);
#pragma unroll
                    for (int mt = 0; mt < 2; ++mt)
#pragma unroll
                        for (int nt = 0; nt < 8; ++nt)
                            mma16(accz[mt][nt], av[mt], wb[par][nt]);
#pragma unroll
                    for (int nt = 0; nt < 8; ++nt)
                        wb[par][nt] = g_wph[jb + nt][kb + 2][lane];
                }
                // register softmax over 4 z-groups (partner lane^1) + hmix
                const __half* qh = (const __half*)qs;
#pragma unroll
                for (int nt = 0; nt < 8; ++nt) {
                    const int pcol = (jb + nt) * 8 - 384 + (lane & 3) * 2;
                    const int u = pcol >> 2;
                    const int gb = pcol & 3;
                    const bool ev = (gb == 0);
                    const float bz0 = bz[gb * 128 + u];
                    const float bz1 = bz[(gb + 1) * 128 + u];
#pragma unroll
                    for (int mt = 0; mt < 2; ++mt) {
                        const int rowa = wm * 32 + mt * 16 + l4;
                        float zi2[2], hm2[2];
#pragma unroll
                        for (int rs = 0; rs < 2; ++rs) {
                            const int row = rowa + rs * 8;
                            const float v0 = accz[mt][nt][rs * 2 + 0] + bz0;
                            const float v1 = accz[mt][nt][rs * 2 + 1] + bz1;
                            float m = fmaxf(v0, v1);
                            m = fmaxf(m, __shfl_xor_sync(0xffffffffu, m, 1));
                            const float e0 = __expf(v0 - m), e1 = __expf(v1 - m);
                            float s = e0 + e1;
                            s += __shfl_xor_sync(0xffffffffu, s, 1);
                            const float inv = 1.f / s;
                            float part;
                            if (ev) {
                                const int c = 128 + u;
                                const float hlv = __half2float(
                                    qh[q2addr(row, c & ~1) * 2 + (c & 1)]);
                                part = e1 * hlv;
                            } else {
                                const float htv = __half2float(
                                    qh[q2addr(row, u & ~1) * 2 + (u & 1)]);
                                const int c = 256 + u;
                                const float hdv = __half2float(
                                    qh[q2addr(row, c & ~1) * 2 + (c & 1)]);
                                part = e0 * htv + e1 * hdv;
                            }
                            const float hm = (part + __shfl_xor_sync(0xffffffffu, part, 1)) * inv;
                            zi2[rs] = e0 * inv;
                            hm2[rs] = hm;
                        }
                        accz[mt][nt][0] = zi2[0]; accz[mt][nt][1] = hm2[0];
                        accz[mt][nt][2] = zi2[1]; accz[mt][nt][3] = hm2[1];
                    }
                }
            }
            __syncthreads();   // all q reads + a2 writes done

            // stash (zi, hmix) as half2 into dead q region, padded stride 132
            unsigned* hmz = smem;
            if ((lane & 1) == 0) {
                const int jb = 48 + wn * 8;
#pragma unroll
                for (int nt = 0; nt < 8; ++nt) {
                    const int pcol = (jb + nt) * 8 - 384 + (lane & 3) * 2;
                    const int u = pcol >> 2;
#pragma unroll
                    for (int mt = 0; mt < 2; ++mt) {
                        const int rowa = wm * 32 + mt * 16 + l4;
                        hmz[rowa * 132 + u]       = packh2(accz[mt][nt][0], accz[mt][nt][1]);
                        hmz[(rowa + 8) * 132 + u] = packh2(accz[mt][nt][2], accz[mt][nt][3]);
                    }
                }
            }
            __syncthreads();

            // ================= GEMM2: N=128, warp = 2mt x 2 jblk ===========
            {
                const int jb = 112 + wn * 2;
                float acc2[2][2][4];
#pragma unroll
                for (int mt = 0; mt < 2; ++mt)
#pragma unroll
                    for (int nt = 0; nt < 2; ++nt)
#pragma unroll
                        for (int i = 0; i < 4; ++i) acc2[mt][nt][i] = 0.f;
                uint2 wb[2][2];
#pragma unroll
                for (int nt = 0; nt < 2; ++nt) {
                    wb[0][nt] = g_wph[jb + nt][0][lane];
                    wb[1][nt] = g_wph[jb + nt][1][lane];
                }
#pragma unroll 2
                for (int kb = 0; kb < KB16; ++kb) {
                    const int par = kb & 1;
                    uint4 av[2];
#pragma unroll
                    for (int mt = 0; mt < 2; ++mt)
                        av[mt] = *(const uint4*)(a2 + (((wm * 2 + mt) * KB16 + kb) * 32 + lane) * 4);
#pragma unroll
                    for (int mt = 0; mt < 2; ++mt)
#pragma unroll
                        for (int nt = 0; nt < 2; ++nt)
                            mma16(acc2[mt][nt], av[mt], wb[par][nt]);
#pragma unroll
                    for (int nt = 0; nt < 2; ++nt)
                        wb[par][nt] = g_wph[jb + nt][kb + 2][lane];
                }
                // h = hmix + zi * tanh(ghat + bij); write fragment h slab
                unsigned* ghout = &g_hhalf[l][rr][hb][0];
#pragma unroll
                for (int nt = 0; nt < 2; ++nt) {
                    const int u0 = (wn * 2 + nt) * 8 + (lane & 3) * 2;
                    const float2 bj = *(const float2*)(bij + u0);
#pragma unroll
                    for (int mt = 0; mt < 2; ++mt) {
#pragma unroll
                        for (int rs = 0; rs < 2; ++rs) {
                            const int rowl = wm * 32 + mt * 16 + l4 + rs * 8;
                            const unsigned m0 = hmz[rowl * 132 + u0];
                            const unsigned m1 = hmz[rowl * 132 + u0 + 1];
                            const __half2 z0 = *(const __half2*)&m0;
                            const __half2 z1 = *(const __half2*)&m1;
                            const float h0 = __high2float(z0) + __low2float(z0) *
                                tanhf(acc2[mt][nt][rs * 2 + 0] + bj.x);
                            const float h1 = __high2float(z1) + __low2float(z1) *
                                tanhf(acc2[mt][nt][rs * 2 + 1] + bj.y);
                            __stcg(ghout + h2addr(rowl, u0), packh2(h0, h1));
                            if (d == NDIAG - 1)
                                *(float2*)(out + (size_t)(b0 + rowl) * UD + u0) =
                                    make_float2(h0, h1);
                        }
                    }
                }
            }
            __threadfence();
            __syncthreads();
            if (tid == 0) *(volatile unsigned*)&g_hflag[l][rr][hb] = 1u;
        }
        base += Td;
    }
}

// ---------------------------------------------------------------------------
extern "C" void kernel_launch(void* const* d_in, const int* in_sizes, int n_in,
                              void* d_out, int out_size)
{
    const float* inputs = (const float*)d_in[0];
    const float* Wr     = (const float*)d_in[1];
    const float* br     = (const float*)d_in[2];
    const float* Wz     = (const float*)d_in[3];
    const float* bz     = (const float*)d_in[4];
    const float* Wij    = (const float*)d_in[5];
    const float* bij    = (const float*)d_in[6];
    const float* WU     = (const float*)d_in[7];
    float* out = (float*)d_out;

    const int SMEM = 2 * QWH * (int)sizeof(unsigned);   // 106496 B
    cudaFuncSetAttribute(spatial_gru_h16,
                         cudaFuncAttributeMaxDynamicSharedMemorySize, SMEM);
    int dev = 0;
    cudaGetDevice(&dev);
    int nsm = 0;
    cudaDeviceGetAttribute(&nsm, cudaDevAttrMultiProcessorCount, dev);
    const int ncta = nsm;   // 1 CTA/SM; grid == resident CTAs (deadlock-free)

    spatial_gru_h16<<<ncta, 512, SMEM>>>(inputs, Wr, br, Wz, bz, Wij, bij,
                                         WU, out, ncta);
}

// round 11
// speedup vs baseline: 3.1156x; 1.3134x over previous
#include <cuda_runtime.h>
#include <cuda_fp16.h>

#define LDIM 80
#define RDIM 80
#define BATCH 128
#define UD 128
#define CD 32
#define DD 416
#define NDIAG 159
#define KB16 26          // 416 / 16
#define KBW 28           // padded for prefetch
#define QWH (2 * KB16 * 32 * 4)   // uint words per 32x416 fp16 fragment tile
#define NTASK 25600               // sum over d of 4*nc

// Fragment-packed fp16 h per (l, r, qb): [2 mb][8 kb][32 lanes] uint4 = 8 KB slab.
__device__ unsigned g_hhalf[LDIM][RDIM][4][2 * 8 * 32 * 4];   // ~105 MB
// fp16 inputs, (l, r, b, c) layout.
__device__ __half   g_sTh[LDIM][RDIM][BATCH][CD];             // ~52 MB
// Fragment-packed fp16 weights: jblk 0..47 Wr; 48..111 Wz interleaved; 112..127 [WU|Wij]
__device__ uint2    g_wph[128][KBW][32];
// Dataflow flags + ticket.
__device__ unsigned g_hflag[LDIM][RDIM][4];
__device__ unsigned g_ticket;
__device__ unsigned g_count;
__device__ unsigned g_sense;

__device__ __forceinline__ unsigned packh2(float a, float b) {
    __half2 h = __floats2half2_rn(a, b);
    return *(unsigned*)&h;
}

__device__ __forceinline__ float fast_tanh(float x) {
    return 1.f - 2.f / (1.f + __expf(2.f * x));
}

__device__ __forceinline__ void mma16(float* c, const uint4& a, const uint2& b) {
    asm volatile(
        "mma.sync.aligned.m16n8k16.row.col.f32.f16.f16.f32 "
        "{%0,%1,%2,%3}, {%4,%5,%6,%7}, {%8,%9}, {%0,%1,%2,%3};\n"
        : "+f"(c[0]), "+f"(c[1]), "+f"(c[2]), "+f"(c[3])
        : "r"(a.x), "r"(a.y), "r"(a.z), "r"(a.w), "r"(b.x), "r"(b.y));
}

// word index (4B) of the half2 (col, col+1), col even, in a q/a2 fragment tile
__device__ __forceinline__ int q2addr(int row, int col) {
    const int mb = row >> 4, rho = row & 15;
    const int kb = col >> 4, kap = col & 15;
    return ((mb * KB16 + kb) * 32 + (rho & 7) * 4 + ((kap >> 1) & 3)) * 4 +
           (rho >> 3) + 2 * (kap >> 3);
}
// same for an h slab (8 kb blocks, 2 mb)
__device__ __forceinline__ int h2addr(int row, int col) {
    const int mb = row >> 4, rho = row & 15;
    const int kb = col >> 4, kap = col & 15;
    return ((mb * 8 + kb) * 32 + (rho & 7) * 4 + ((kap >> 1) & 3)) * 4 +
           (rho >> 3) + 2 * (kap >> 3);
}

__device__ __forceinline__ void gbar(int ncta, unsigned& sense) {
    __syncthreads();
    if (threadIdx.x == 0) {
        __threadfence();
        unsigned arrived = atomicAdd(&g_count, 1u) + 1u;
        if (arrived == (unsigned)ncta) {
            g_count = 0u;
            __threadfence();
            atomicAdd(&g_sense, 1u);
        } else {
            while ((int)(*(volatile unsigned*)&g_sense - (sense + 1u)) < 0) {
                __nanosleep(64);
            }
        }
    }
    sense += 1u;
    __syncthreads();
}

__global__ __launch_bounds__(512, 1) void spatial_gru_q32(
    const float* __restrict__ inputs, const float* __restrict__ Wr,
    const float* __restrict__ br, const float* __restrict__ Wz,
    const float* __restrict__ bz, const float* __restrict__ Wij,
    const float* __restrict__ bij, const float* __restrict__ WU,
    float* __restrict__ out, int ncta)
{
    extern __shared__ unsigned smem[];
    unsigned* qs = smem;
    unsigned* a2 = smem + QWH;
    const int tid = threadIdx.x;
    const int cta = blockIdx.x;
    const int gtid = cta * 512 + tid;
    const int gstride = ncta * 512;
    unsigned sense = *(volatile unsigned*)&g_sense;

    // ---------------- stage 0 -------------------------------------------
    if (gtid == 0) g_ticket = 0u;
    // pack weights -> fp16 fragments
    for (int idx = gtid; idx < 128 * KB16 * 32; idx += gstride) {
        const int lane = idx & 31;
        const int kb = (idx >> 5) % KB16;
        const int jblk = (idx >> 5) / KB16;
        const int jp = jblk * 8 + (lane >> 2);
        const int k = kb * 16 + (lane & 3) * 2;
        float w0, w1, w8, w9;
        if (jblk < 48) {
            const float* p = Wr + (size_t)jp * DD + k;
            w0 = p[0]; w1 = p[1]; w8 = p[8]; w9 = p[9];
        } else if (jblk < 112) {
            const int jz = jp - 384;
            const int j = (jz & 3) * 128 + (jz >> 2);
            const float* p = Wz + (size_t)j * DD + k;
            w0 = p[0]; w1 = p[1]; w8 = p[8]; w9 = p[9];
        } else {
            const int u = jp - 896;
            if (k < 384) {
                const float* p = WU + (size_t)u * 384 + k;
                w0 = p[0]; w1 = p[1]; w8 = p[8]; w9 = p[9];
            } else {
                const float* p = Wij + (size_t)u * 32 + (k - 384);
                w0 = p[0]; w1 = p[1]; w8 = p[8]; w9 = p[9];
            }
        }
        g_wph[jblk][kb][lane] = make_uint2(packh2(w0, w1), packh2(w8, w9));
    }
    // transpose inputs (B,C,L,R) -> fp16 (L,R,B,C)
    for (int idx = gtid; idx < BATCH * (CD / 2) * LDIM * (RDIM / 4); idx += gstride) {
        const int r4 = idx % (RDIM / 4);
        int t2 = idx / (RDIM / 4);
        const int l = t2 % LDIM; t2 /= LDIM;
        const int c2 = t2 & 15;
        const int b = t2 >> 4;
        const int c = c2 * 2, r0 = r4 * 4;
        const float* p0 = inputs + (((size_t)b * CD + c) * LDIM + l) * RDIM + r0;
        const float4 x0 = *(const float4*)p0;
        const float4 x1 = *(const float4*)(p0 + LDIM * RDIM);
        *(unsigned*)&g_sTh[l][r0 + 0][b][c] = packh2(x0.x, x1.x);
        *(unsigned*)&g_sTh[l][r0 + 1][b][c] = packh2(x0.y, x1.y);
        *(unsigned*)&g_sTh[l][r0 + 2][b][c] = packh2(x0.z, x1.z);
        *(unsigned*)&g_sTh[l][r0 + 3][b][c] = packh2(x0.w, x1.w);
    }
    for (int idx = gtid; idx < LDIM * RDIM * 4; idx += gstride)
        ((unsigned*)g_hflag)[idx] = 0u;
    gbar(ncta, sense);

    const int warp = tid >> 5, lane = tid & 31;
    const int l4 = lane >> 2;
    const int wm = warp >> 3;   // m-block: local rows [wm*16, wm*16+16)
    const int wn = warp & 7;    // n-warp index

    // dynamic ticket walk state
    int dcur = 0;
    int dbase = 0;
    int nc = 1;   // nc(0) = 1

    int tkt = tid == 0 ? (int)atomicAdd(&g_ticket, 1u) : 0;
    __shared__ int s_tkt;
    for (;;) {
        if (tid == 0) s_tkt = tkt;
        __syncthreads();
        const int t = s_tkt;
        if (t >= NTASK) break;
        // advance diagonal pointer
        while (t >= dbase + 4 * nc) {
            dbase += 4 * nc;
            ++dcur;
            const int lo = (dcur > RDIM - 1) ? dcur - (RDIM - 1) : 0;
            const int hi = (dcur < LDIM - 1) ? dcur : LDIM - 1;
            nc = hi - lo + 1;
        }
        const int d = dcur;
        const int l0 = (d > RDIM - 1) ? d - (RDIM - 1) : 0;
        const int ti = t - dbase;
        const int ci = ti >> 2, qb = ti & 3;
        const int l = l0 + ci, rr = d - l;
        const int b0 = qb * 32;

        // -------- wait for neighbor h flags (tight poll) --------
        if (tid < 3) {
            volatile unsigned* f = 0;
            if (tid == 0)      { if (rr > 0) f = &g_hflag[l][rr - 1][qb]; }
            else if (tid == 1) { if (l > 0)  f = &g_hflag[l - 1][rr][qb]; }
            else               { if (l > 0 && rr > 0) f = &g_hflag[l - 1][rr - 1][qb]; }
            if (f) {
                while (*f == 0u) { }
                __threadfence();
            }
        }
        __syncthreads();

        const uint4* ghtop  = (l > 0)  ? (const uint4*)&g_hhalf[l - 1][rr][qb][0] : (const uint4*)0;
        const uint4* ghleft = (rr > 0) ? (const uint4*)&g_hhalf[l][rr - 1][qb][0] : (const uint4*)0;
        const uint4* ghdiag = (l > 0 && rr > 0)
                             ? (const uint4*)&g_hhalf[l - 1][rr - 1][qb][0] : (const uint4*)0;

        // -------- build q: h regions are direct fragment copies --------
        for (int idx = tid; idx < 1536; idx += 512) {
            const int ln = idx & 31;
            const int kq = (idx >> 5) % 24;
            const int mb = (idx >> 5) / 24;
            const uint4* src;
            if (kq < 8)       src = ghtop;
            else if (kq < 16) src = ghleft;
            else              src = ghdiag;
            uint4 v = make_uint4(0u, 0u, 0u, 0u);
            if (src) v = src[(mb * 8 + (kq & 7)) * 32 + ln];
            *(uint4*)(qs + ((mb * KB16 + kq) * 32 + ln) * 4) = v;
        }
        // s region (q kb 24,25)
        if (tid < 128) {
            const int ln = tid & 31;
            const int kb2 = (tid >> 5) & 1;
            const int mb = tid >> 6;
            const int row = b0 + mb * 16 + (ln >> 2);
            const int c0 = kb2 * 16 + (ln & 3) * 2;
            const __half* s0 = &g_sTh[l][rr][row][0];
            const __half* s1 = &g_sTh[l][rr][row + 8][0];
            uint4 v;
            v.x = *(const unsigned*)(s0 + c0);
            v.y = *(const unsigned*)(s1 + c0);
            v.z = *(const unsigned*)(s0 + c0 + 8);
            v.w = *(const unsigned*)(s1 + c0 + 8);
            *(uint4*)(qs + ((mb * KB16 + 24 + kb2) * 32 + ln) * 4) = v;
        }
        __syncthreads();

        // ================= GEMM1-r: N=384, warp = 1mb x 6 jblk =========
        {
            const int jb = wn * 6;
            float acc[6][4];
#pragma unroll
            for (int nt = 0; nt < 6; ++nt)
#pragma unroll
                for (int i = 0; i < 4; ++i) acc[nt][i] = 0.f;
            uint2 wb[2][6];
#pragma unroll
            for (int nt = 0; nt < 6; ++nt) {
                wb[0][nt] = g_wph[jb + nt][0][lane];
                wb[1][nt] = g_wph[jb + nt][1][lane];
            }
#pragma unroll 2
            for (int kb = 0; kb < KB16; ++kb) {
                const int par = kb & 1;
                const uint4 av = *(const uint4*)(qs + ((wm * KB16 + kb) * 32 + lane) * 4);
#pragma unroll
                for (int nt = 0; nt < 6; ++nt)
                    mma16(acc[nt], av, wb[par][nt]);
#pragma unroll
                for (int nt = 0; nt < 6; ++nt)
                    wb[par][nt] = g_wph[jb + nt][kb + 2][lane];
            }
            // a2 = sigmoid(r + br) * h (block-swapped source)
#pragma unroll
            for (int nt = 0; nt < 6; ++nt) {
                const int col0 = (jb + nt) * 8 + (lane & 3) * 2;
                const float b0r = br[col0], b1r = br[col0 + 1];
                const int qc0 = (col0 < 128) ? col0 + 128
                              : (col0 < 256) ? col0 - 128 : col0;
#pragma unroll
                for (int rs = 0; rs < 2; ++rs) {
                    const int rowl = wm * 16 + l4 + rs * 8;
                    const unsigned hv = qs[q2addr(rowl, qc0)];
                    const __half2 hh = *(const __half2*)&hv;
                    const float p0 = acc[nt][rs * 2 + 0] + b0r;
                    const float p1 = acc[nt][rs * 2 + 1] + b1r;
                    const float v0 = __low2float(hh) / (1.f + __expf(-p0));
                    const float v1 = __high2float(hh) / (1.f + __expf(-p1));
                    a2[q2addr(rowl, col0)] = packh2(v0, v1);
                }
            }
        }
        // copy s blocks q -> a2
        if (tid < 128) {
            const int ln = tid & 31;
            const int kb2 = (tid >> 5) & 1;
            const int mb = tid >> 6;
            const int off = (mb * KB16 + 24 + kb2) * 32 + ln;
            ((uint4*)a2)[off] = ((const uint4*)qs)[off];
        }

        // ================= GEMM1-z: N=512 interleaved, 1mb x 8 jblk ====
        float accz[8][4];
        {
            const int jb = 48 + wn * 8;
#pragma unroll
            for (int nt = 0; nt < 8; ++nt)
#pragma unroll
                for (int i = 0; i < 4; ++i) accz[nt][i] = 0.f;
            uint2 wb[2][8];
#pragma unroll
            for (int nt = 0; nt < 8; ++nt) {
                wb[0][nt] = g_wph[jb + nt][0][lane];
                wb[1][nt] = g_wph[jb + nt][1][lane];
            }
#pragma unroll 2
            for (int kb = 0; kb < KB16; ++kb) {
                const int par = kb & 1;
                const uint4 av = *(const uint4*)(qs + ((wm * KB16 + kb) * 32 + lane) * 4);
#pragma unroll
                for (int nt = 0; nt < 8; ++nt)
                    mma16(accz[nt], av, wb[par][nt]);
#pragma unroll
                for (int nt = 0; nt < 8; ++nt)
                    wb[par][nt] = g_wph[jb + nt][kb + 2][lane];
            }
            // register softmax over 4 z-groups (partner lane^1) + hmix
            const __half* qh = (const __half*)qs;
#pragma unroll
            for (int nt = 0; nt < 8; ++nt) {
                const int pcol = (jb + nt) * 8 - 384 + (lane & 3) * 2;
                const int u = pcol >> 2;
                const int gb = pcol & 3;
                const bool ev = (gb == 0);
                const float bz0 = bz[gb * 128 + u];
                const float bz1 = bz[(gb + 1) * 128 + u];
#pragma unroll
                for (int rs = 0; rs < 2; ++rs) {
                    const int row = wm * 16 + l4 + rs * 8;
                    const float v0 = accz[nt][rs * 2 + 0] + bz0;
                    const float v1 = accz[nt][rs * 2 + 1] + bz1;
                    float m = fmaxf(v0, v1);
                    m = fmaxf(m, __shfl_xor_sync(0xffffffffu, m, 1));
                    const float e0 = __expf(v0 - m), e1 = __expf(v1 - m);
                    float s = e0 + e1;
                    s += __shfl_xor_sync(0xffffffffu, s, 1);
                    const float inv = 1.f / s;
                    float part;
                    if (ev) {
                        const int c = 128 + u;
                        const float hlv = __half2float(
                            qh[q2addr(row, c & ~1) * 2 + (c & 1)]);
                        part = e1 * hlv;
                    } else {
                        const float htv = __half2float(
                            qh[q2addr(row, u & ~1) * 2 + (u & 1)]);
                        const int c = 256 + u;
                        const float hdv = __half2float(
                            qh[q2addr(row, c & ~1) * 2 + (c & 1)]);
                        part = e0 * htv + e1 * hdv;
                    }
                    const float hm = (part + __shfl_xor_sync(0xffffffffu, part, 1)) * inv;
                    accz[nt][rs * 2 + 0] = e0 * inv;   // zi (even lanes meaningful)
                    accz[nt][rs * 2 + 1] = hm;
                }
            }
        }
        __syncthreads();   // all q reads + a2 writes done

        // stash (zi, hmix) as half2 into dead q region, padded stride 132
        unsigned* hmz = smem;
        if ((lane & 1) == 0) {
            const int jb = 48 + wn * 8;
#pragma unroll
            for (int nt = 0; nt < 8; ++nt) {
                const int pcol = (jb + nt) * 8 - 384 + (lane & 3) * 2;
                const int u = pcol >> 2;
#pragma unroll
                for (int rs = 0; rs < 2; ++rs) {
                    const int row = wm * 16 + l4 + rs * 8;
                    hmz[row * 132 + u] = packh2(accz[nt][rs * 2 + 0],
                                                accz[nt][rs * 2 + 1]);
                }
            }
        }
        __syncthreads();

        // ================= GEMM2: N=128, warp = 1mb x 2 jblk ===========
        {
            const int jb = 112 + wn * 2;
            float acc2[2][4];
#pragma unroll
            for (int nt = 0; nt < 2; ++nt)
#pragma unroll
                for (int i = 0; i < 4; ++i) acc2[nt][i] = 0.f;
            uint2 wb[2][2];
#pragma unroll
            for (int nt = 0; nt < 2; ++nt) {
                wb[0][nt] = g_wph[jb + nt][0][lane];
                wb[1][nt] = g_wph[jb + nt][1][lane];
            }
#pragma unroll 2
            for (int kb = 0; kb < KB16; ++kb) {
                const int par = kb & 1;
                const uint4 av = *(const uint4*)(a2 + ((wm * KB16 + kb) * 32 + lane) * 4);
#pragma unroll
                for (int nt = 0; nt < 2; ++nt)
                    mma16(acc2[nt], av, wb[par][nt]);
#pragma unroll
                for (int nt = 0; nt < 2; ++nt)
                    wb[par][nt] = g_wph[jb + nt][kb + 2][lane];
            }
            // h = hmix + zi * tanh(ghat + bij); write fragment h slab
            unsigned* ghout = &g_hhalf[l][rr][qb][0];
#pragma unroll
            for (int nt = 0; nt < 2; ++nt) {
                const int u0 = (wn * 2 + nt) * 8 + (lane & 3) * 2;
                const float2 bj = *(const float2*)(bij + u0);
#pragma unroll
                for (int rs = 0; rs < 2; ++rs) {
                    const int rowl = wm * 16 + l4 + rs * 8;
                    const unsigned m0 = hmz[rowl * 132 + u0];
                    const unsigned m1 = hmz[rowl * 132 + u0 + 1];
                    const __half2 z0 = *(const __half2*)&m0;
                    const __half2 z1 = *(const __half2*)&m1;
                    const float h0 = __high2float(z0) + __low2float(z0) *
                        fast_tanh(acc2[nt][rs * 2 + 0] + bj.x);
                    const float h1 = __high2float(z1) + __low2float(z1) *
                        fast_tanh(acc2[nt][rs * 2 + 1] + bj.y);
                    __stcg(ghout + h2addr(rowl, u0), packh2(h0, h1));
                    if (d == NDIAG - 1)
                        *(float2*)(out + (size_t)(b0 + rowl) * UD + u0) =
                            make_float2(h0, h1);
                }
            }
        }
        __threadfence();
        __syncthreads();
        if (tid == 0) {
            *(volatile unsigned*)&g_hflag[l][rr][qb] = 1u;
            tkt = (int)atomicAdd(&g_ticket, 1u);
        }
    }
}

// ---------------------------------------------------------------------------
extern "C" void kernel_launch(void* const* d_in, const int* in_sizes, int n_in,
                              void* d_out, int out_size)
{
    const float* inputs = (const float*)d_in[0];
    const float* Wr     = (const float*)d_in[1];
    const float* br     = (const float*)d_in[2];
    const float* Wz     = (const float*)d_in[3];
    const float* bz     = (const float*)d_in[4];
    const float* Wij    = (const float*)d_in[5];
    const float* bij    = (const float*)d_in[6];
    const float* WU     = (const float*)d_in[7];
    float* out = (float*)d_out;

    const int SMEM = 2 * QWH * (int)sizeof(unsigned);   // 53248 B
    cudaFuncSetAttribute(spatial_gru_q32,
                         cudaFuncAttributeMaxDynamicSharedMemorySize, SMEM);
    int dev = 0;
    cudaGetDevice(&dev);
    int nsm = 0;
    cudaDeviceGetAttribute(&nsm, cudaDevAttrMultiProcessorCount, dev);
    const int ncta = nsm;   // 1 CTA/SM; grid == resident CTAs (deadlock-free)

    spatial_gru_q32<<<ncta, 512, SMEM>>>(inputs, Wr, br, Wz, bz, Wij, bij,
                                         WU, out, ncta);
}